// round 14
// baseline (speedup 1.0000x reference)
#include <cuda_runtime.h>
#include <cstdint>

// ---------------------------------------------------------------------------
// Problem constants
// ---------------------------------------------------------------------------
#define TOKENS 8192
#define IN_F   4096
#define OUT_F  14336

#define TM 128
#define TN 64
#define TKC 64                         // K bytes per chunk / per smem stage
#define NCHUNK (IN_F / TKC)            // 64
#define NMT (TOKENS / TM)              // 64
#define NNT (OUT_F / TN)               // 224
#define GROUP_M 8

#define STAGES 4
#define OFF_ALO 8192
#define OFF_B   16384
#define STAGE_BYTES 20480              // A_hi 8K + A_lo 8K + B 4K
#define SMEM_DYN (STAGES * STAGE_BYTES)   // 81920

// ---------------------------------------------------------------------------
// Device-global scratch (static allocation — no runtime allocs allowed)
// ---------------------------------------------------------------------------
__device__ int8_t g_qh[(size_t)TOKENS * IN_F];   // high s8 plane of quantized x
__device__ int8_t g_ql[(size_t)TOKENS * IN_F];   // low  s8 plane
__device__ int8_t g_w8[(size_t)OUT_F * IN_F];    // expanded nibbles (0..15) as s8
__device__ float  g_rs[TOKENS];                  // per-row sum of x
__device__ float  g_stq[TOKENS];                 // per-row quant scale s_t
__device__ float  g_inv[TOKENS];                 // 1 / s_t

// ---------------------------------------------------------------------------
// small helpers
// ---------------------------------------------------------------------------
__device__ __forceinline__ uint32_t smem_u32(const void* p) {
    uint32_t a;
    asm("{ .reg .u64 t; cvta.to.shared.u64 t, %1; cvt.u32.u64 %0, t; }"
        : "=r"(a) : "l"(p));
    return a;
}

__device__ __forceinline__ void cp_async16(uint32_t dst, const void* src) {
    asm volatile("cp.async.cg.shared.global [%0], [%1], 16;"
                 :: "r"(dst), "l"(src) : "memory");
}
__device__ __forceinline__ void cp_commit() {
    asm volatile("cp.async.commit_group;" ::: "memory");
}

__device__ __forceinline__ void ldsm_x4(uint32_t* a, uint32_t addr) {
    asm volatile("ldmatrix.sync.aligned.m8n8.x4.shared.b16 {%0,%1,%2,%3}, [%4];"
                 : "=r"(a[0]), "=r"(a[1]), "=r"(a[2]), "=r"(a[3]) : "r"(addr));
}

__device__ __forceinline__ void mma_s8(int* d, const uint32_t* a, const uint32_t* b) {
    asm volatile(
        "mma.sync.aligned.m16n8k32.row.col.s32.s8.s8.s32 "
        "{%0,%1,%2,%3}, {%4,%5,%6,%7}, {%8,%9}, {%0,%1,%2,%3};"
        : "+r"(d[0]), "+r"(d[1]), "+r"(d[2]), "+r"(d[3])
        : "r"(a[0]), "r"(a[1]), "r"(a[2]), "r"(a[3]), "r"(b[0]), "r"(b[1]));
}

__device__ __forceinline__ void lds128(uint32_t* v, uint32_t addr) {
    asm volatile("ld.shared.v4.b32 {%0,%1,%2,%3}, [%4];"
                 : "=r"(v[0]), "=r"(v[1]), "=r"(v[2]), "=r"(v[3]) : "r"(addr));
}

// ---------------------------------------------------------------------------
// Preprocess 1: per-row sum + quantization scale
// ---------------------------------------------------------------------------
__global__ __launch_bounds__(256)
void rowstat_kernel(const float* __restrict__ x) {
    const int row = blockIdx.x;
    const float4* xr = (const float4*)(x + (size_t)row * IN_F);
    float s = 0.f, m = 0.f;
#pragma unroll
    for (int i = 0; i < 4; i++) {
        float4 f = __ldg(xr + threadIdx.x + i * 256);
        s += (f.x + f.y) + (f.z + f.w);
        m = fmaxf(m, fmaxf(fmaxf(fabsf(f.x), fabsf(f.y)), fmaxf(fabsf(f.z), fabsf(f.w))));
    }
#pragma unroll
    for (int o = 16; o; o >>= 1) {
        s += __shfl_xor_sync(0xFFFFFFFFu, s, o);
        m = fmaxf(m, __shfl_xor_sync(0xFFFFFFFFu, m, o));
    }
    __shared__ float rs[8], rm[8];
    if ((threadIdx.x & 31) == 0) { rs[threadIdx.x >> 5] = s; rm[threadIdx.x >> 5] = m; }
    __syncthreads();
    if (threadIdx.x == 0) {
        float ts = 0.f, tm = 0.f;
#pragma unroll
        for (int j = 0; j < 8; j++) { ts += rs[j]; tm = fmaxf(tm, rm[j]); }
        g_rs[row] = ts;
        if (tm > 0.f) { g_stq[row] = tm / 32512.f; g_inv[row] = 32512.f / tm; }
        else          { g_stq[row] = 0.f;          g_inv[row] = 0.f; }
    }
}

// ---------------------------------------------------------------------------
// Preprocess 2: quantize x -> (qh, ql) s8 planes.
// ---------------------------------------------------------------------------
__global__ __launch_bounds__(256)
void quantx_kernel(const float* __restrict__ x) {
    const int id  = blockIdx.x * 256 + threadIdx.x;
    const int row = id >> 9;
    const int kc  = (id & 511) * 8;
    const float inv = __ldg(g_inv + row);
    const float4* p = (const float4*)(x + (size_t)row * IN_F + kc);
    float4 f0 = __ldg(p), f1 = __ldg(p + 1);
    int q[8];
    q[0] = __float2int_rn(f0.x * inv); q[1] = __float2int_rn(f0.y * inv);
    q[2] = __float2int_rn(f0.z * inv); q[3] = __float2int_rn(f0.w * inv);
    q[4] = __float2int_rn(f1.x * inv); q[5] = __float2int_rn(f1.y * inv);
    q[6] = __float2int_rn(f1.z * inv); q[7] = __float2int_rn(f1.w * inv);
    uint32_t h0 = 0, h1 = 0, l0 = 0, l1 = 0;
#pragma unroll
    for (int i = 0; i < 4; i++) {
        int qh = (q[i] + 128) >> 8;
        int ql = q[i] - (qh << 8);
        h0 |= ((uint32_t)qh & 0xFFu) << (8 * i);
        l0 |= ((uint32_t)ql & 0xFFu) << (8 * i);
        int qh2 = (q[4 + i] + 128) >> 8;
        int ql2 = q[4 + i] - (qh2 << 8);
        h1 |= ((uint32_t)qh2 & 0xFFu) << (8 * i);
        l1 |= ((uint32_t)ql2 & 0xFFu) << (8 * i);
    }
    *(uint2*)(g_qh + (size_t)row * IN_F + kc) = make_uint2(h0, h1);
    *(uint2*)(g_ql + (size_t)row * IN_F + kc) = make_uint2(l0, l1);
}

// ---------------------------------------------------------------------------
// Preprocess 3: expand packed nibbles to s8 bytes (0..15 exact).
// ---------------------------------------------------------------------------
__global__ __launch_bounds__(256)
void expw_kernel(const int* __restrict__ pw) {
    const size_t id = (size_t)blockIdx.x * 256 + threadIdx.x;
    int4 p = __ldg((const int4*)pw + id);
    uint32_t w0 = (uint32_t)(p.x & 0xF) | ((uint32_t)(p.x & 0xF0) << 4)
                | ((uint32_t)(p.y & 0xF) << 16) | ((uint32_t)(p.y & 0xF0) << 20);
    uint32_t w1 = (uint32_t)(p.z & 0xF) | ((uint32_t)(p.z & 0xF0) << 4)
                | ((uint32_t)(p.w & 0xF) << 16) | ((uint32_t)(p.w & 0xF0) << 20);
    ((uint2*)g_w8)[id] = make_uint2(w0, w1);
}

// ---------------------------------------------------------------------------
// GEMM: 128x64 tile, 256 threads, 2 CTAs/SM.  R13 skeleton with the binding
// constraint (dp4a/fma pipe at ~85%) rebalanced toward the tensor pipe:
//   warps 0-3 (tensor): hi plane cols 0..63 (32 mma) + LO plane cols 0..7
//     (4 mma, reusing the b[0] fragments and the a registers; +8 acc regs).
//   warps 4-7 (fma):    lo plane cols 8..63 only (896 dp4a, compact acc[56]).
// Epilogue: cols 0..7 combined fully in-register by tensor warps; fma warps
// publish lo cols 8..63 via SMEM (pitch 57); tensor warps store all.
// ---------------------------------------------------------------------------
__global__ __launch_bounds__(256, 2)
void gemm_kernel(const float* __restrict__ scales, const float* __restrict__ zps,
                 float* __restrict__ out) {
    extern __shared__ char smem[];
    const uint32_t sbase = smem_u32(smem);

    const int tid = threadIdx.x;
    const int l   = tid & 31;
    const int wid = tid >> 5;
    const bool tw = (wid < 4);         // tensor warp?
    const int wm  = wid & 3;           // row-block (0..3) for BOTH roles

    const int per_group = GROUP_M * NNT;
    const int grp = blockIdx.x / per_group;
    const int rem = blockIdx.x - grp * per_group;
    const int m0 = (grp * GROUP_M + (rem % GROUP_M)) * TM;
    const int n0 = (rem / GROUP_M) * TN;

    // ---- pipeline fill (R8 pattern): per thread 2x A_hi, 2x A_lo, 1x B ----
    const int frow = tid >> 2;              // 0..63
    const int fg   = tid & 3;
    const uint32_t fsw = (uint32_t)((fg ^ ((frow >> 1) & 3)) << 4);
    const uint32_t d1 = (uint32_t)frow * 64 + fsw;
    const uint32_t d2 = d1 + 64 * 64;
    const int8_t* srcA_h1 = g_qh + (size_t)(m0 + frow) * IN_F + fg * 16;
    const int8_t* srcA_h2 = g_qh + (size_t)(m0 + 64 + frow) * IN_F + fg * 16;
    const int8_t* srcA_l1 = g_ql + (size_t)(m0 + frow) * IN_F + fg * 16;
    const int8_t* srcA_l2 = g_ql + (size_t)(m0 + 64 + frow) * IN_F + fg * 16;
    const int8_t* srcB    = g_w8 + (size_t)(n0 + frow) * IN_F + fg * 16;

#define FILL(ch, stage) do {                                                  \
        uint32_t st_ = sbase + (uint32_t)(stage) * STAGE_BYTES;               \
        int k0_ = (ch) * TKC;                                                 \
        cp_async16(st_ + d1,                 srcA_h1 + k0_);                  \
        cp_async16(st_ + d2,                 srcA_h2 + k0_);                  \
        cp_async16(st_ + OFF_ALO + d1,       srcA_l1 + k0_);                  \
        cp_async16(st_ + OFF_ALO + d2,       srcA_l2 + k0_);                  \
        cp_async16(st_ + OFF_B + d1,         srcB    + k0_);                  \
    } while (0)

    FILL(0, 0); cp_commit();
    FILL(1, 1); cp_commit();
    FILL(2, 2); cp_commit();

    // tensor-warp lane constants (ldmatrix)
    const int lm_row = (((l >> 3) & 1) << 3) + (l & 7);
    const int lm_g   = (l >> 4) & 1;

    // fma-warp lane constants
    const int r0 = l >> 2;                       // 8 row positions
    const uint32_t swA = (uint32_t)((r0 >> 1) & 3);
    const uint32_t swB = (uint32_t)(l & 3);
    const uint32_t aRowBase = (uint32_t)(wm * 32 + r0) * 64;

    // accumulators:
    //   tensor -> acc[mt*32+nt*4+c] (hi, 64) + accLo[mt*4+c] (lo cols 0..7)
    //   fma    -> acc[ri*14 + (ci-2)] (lo cols 8..63, 56 used)
    int acc[64];
    int accLo[8];
#pragma unroll
    for (int i = 0; i < 64; i++) acc[i] = 0;
#pragma unroll
    for (int i = 0; i < 8; i++) accLo[i] = 0;

    for (int ch = 0; ch < NCHUNK; ch++) {
        asm volatile("cp.async.wait_group 2;" ::: "memory");
        __syncthreads();   // single per-chunk barrier (R13-proven)

        if (ch + STAGES - 1 < NCHUNK) FILL(ch + STAGES - 1, (ch + STAGES - 1) & 3);
        cp_commit();

        const uint32_t st = sbase + (uint32_t)(ch & 3) * STAGE_BYTES;

        if (tw) {
            // ===== tensor warps: hi cols 0..63 + lo cols 0..7 =====
#pragma unroll
            for (int ks = 0; ks < 2; ks++) {
                uint32_t b[8][2];
#pragma unroll
                for (int nt = 0; nt < 8; nt++) {
                    int rn = nt * 8 + (l >> 2);
                    uint32_t rb = st + OFF_B + (uint32_t)rn * 64 + 4 * (l & 3);
                    int rm = (rn >> 1) & 3;
                    uint32_t a0 = rb + (uint32_t)(((ks * 2 + 0) ^ rm) << 4);
                    uint32_t a1 = rb + (uint32_t)(((ks * 2 + 1) ^ rm) << 4);
                    asm volatile("ld.shared.b32 %0, [%1];" : "=r"(b[nt][0]) : "r"(a0));
                    asm volatile("ld.shared.b32 %0, [%1];" : "=r"(b[nt][1]) : "r"(a1));
                }
#pragma unroll
                for (int mt = 0; mt < 2; mt++) {
                    int row = wm * 32 + mt * 16 + lm_row;
                    uint32_t ra = st + (uint32_t)row * 64
                                + (uint32_t)((((ks * 2 + lm_g) ^ ((row >> 1) & 3))) << 4);
                    uint32_t a[4];
                    ldsm_x4(a, ra);                       // hi-plane fragments
#pragma unroll
                    for (int nt = 0; nt < 8; nt++)
                        mma_s8(&acc[mt * 32 + nt * 4], a, b[nt]);
                    ldsm_x4(a, ra + OFF_ALO);             // lo-plane fragments
                    mma_s8(&accLo[mt * 4], a, b[0]);      // lo cols 0..7
                }
            }
        } else {
            // ===== fma warps: lo plane cols 8..63 via dp4a =====
#pragma unroll
            for (int g = 0; g < 4; g++) {
                uint32_t a4[4][4];
                const uint32_t aGran = (uint32_t)((g ^ swA) << 4);
#pragma unroll
                for (int ri = 0; ri < 4; ri++)
                    lds128(a4[ri], st + OFF_ALO + aRowBase + (uint32_t)(ri * 8 * 64) + aGran);
                const uint32_t bGran = (uint32_t)((g ^ swB) << 4);
#pragma unroll
                for (int ci = 2; ci < 16; ci++) {
                    uint32_t b4[4];
                    int n = 2 * (l & 3) + (ci & 1) + 8 * (ci >> 1);   // cols 8..63
                    lds128(b4, st + OFF_B + (uint32_t)n * 64 + bGran);
#pragma unroll
                    for (int w = 0; w < 4; w++)
#pragma unroll
                        for (int ri = 0; ri < 4; ri++)
                            acc[ri * 14 + (ci - 2)] = __dp4a((int)a4[ri][w], (int)b4[w],
                                                             acc[ri * 14 + (ci - 2)]);
                }
            }
        }
    }
    asm volatile("cp.async.wait_group 0;" ::: "memory");
    __syncthreads();

    // ---- fma warps publish lo-plane sums for cols 8..63 (pitch 57) ----
    int* sD = (int*)smem;                       // [128][57]
    if (!tw) {
#pragma unroll
        for (int ri = 0; ri < 4; ri++)
#pragma unroll
            for (int ci = 2; ci < 16; ci++) {
                int row = wm * 32 + r0 + 8 * ri;
                int col = 2 * (l & 3) + (ci & 1) + 8 * (ci >> 1);     // 8..63
                sD[row * 57 + (col - 8)] = acc[ri * 14 + (ci - 2)];
            }
    }
    __syncthreads();

    // ---- epilogue (tensor warps): out = sc*(s_t*((hi<<8)+lo) - zp*rs) ----
    if (tw) {
#pragma unroll
        for (int mt = 0; mt < 2; mt++) {
            const int lr0 = wm * 32 + mt * 16 + (l >> 2);
            const int rr0 = m0 + lr0;
            const float st0 = __ldg(g_stq + rr0),     rs0 = __ldg(g_rs + rr0);
            const float st1 = __ldg(g_stq + rr0 + 8), rs1 = __ldg(g_rs + rr0 + 8);
#pragma unroll
            for (int nt = 0; nt < 8; nt++) {
                const int lc = nt * 8 + 2 * (l & 3);
                const int c  = n0 + lc;
                const float sc0 = __ldg(scales + c), sc1 = __ldg(scales + c + 1);
                const float zp0 = __ldg(zps + c),    zp1 = __ldg(zps + c + 1);
                int L0, L1, L2, L3;
                if (nt == 0) {                    // lo cols 0..7: in-register
                    L0 = accLo[mt * 4 + 0];
                    L1 = accLo[mt * 4 + 1];
                    L2 = accLo[mt * 4 + 2];
                    L3 = accLo[mt * 4 + 3];
                } else {                          // lo cols 8..63: from SMEM
                    L0 = sD[lr0 * 57 + (lc - 8)];
                    L1 = sD[lr0 * 57 + (lc - 7)];
                    L2 = sD[(lr0 + 8) * 57 + (lc - 8)];
                    L3 = sD[(lr0 + 8) * 57 + (lc - 7)];
                }
                int A0 = (acc[mt * 32 + nt * 4 + 0] << 8) + L0;
                int A1 = (acc[mt * 32 + nt * 4 + 1] << 8) + L1;
                int A2 = (acc[mt * 32 + nt * 4 + 2] << 8) + L2;
                int A3 = (acc[mt * 32 + nt * 4 + 3] << 8) + L3;
                float2 v0 = make_float2(sc0 * (st0 * (float)A0 - zp0 * rs0),
                                        sc1 * (st0 * (float)A1 - zp1 * rs0));
                float2 v1 = make_float2(sc0 * (st1 * (float)A2 - zp0 * rs1),
                                        sc1 * (st1 * (float)A3 - zp1 * rs1));
                *(float2*)(out + (size_t)rr0 * OUT_F + c)       = v0;
                *(float2*)(out + (size_t)(rr0 + 8) * OUT_F + c) = v1;
            }
        }
    }
#undef FILL
}

// ---------------------------------------------------------------------------
// Launch
// ---------------------------------------------------------------------------
extern "C" void kernel_launch(void* const* d_in, const int* in_sizes, int n_in,
                              void* d_out, int out_size) {
    const float* x  = (const float*)d_in[0];
    const int*   pw = (const int*)d_in[1];
    const float* sc = (const float*)d_in[2];
    const float* zp = (const float*)d_in[3];
    float* out = (float*)d_out;

    cudaFuncSetAttribute(gemm_kernel, cudaFuncAttributeMaxDynamicSharedMemorySize, SMEM_DYN);

    rowstat_kernel<<<TOKENS, 256>>>(x);
    quantx_kernel<<<(TOKENS * (IN_F / 8)) / 256, 256>>>(x);
    expw_kernel<<<(int)(((size_t)OUT_F * (IN_F / 2) / 4) / 256), 256>>>(pw);
    gemm_kernel<<<NMT * NNT, 256, SMEM_DYN>>>(sc, zp, out);

    (void)in_sizes; (void)n_in; (void)out_size;
}

// round 16
// speedup vs baseline: 1.0368x; 1.0368x over previous
#include <cuda_runtime.h>
#include <cstdint>

// ---------------------------------------------------------------------------
// Problem constants
// ---------------------------------------------------------------------------
#define TOKENS 8192
#define IN_F   4096
#define OUT_F  14336

#define TM 128
#define TN 64
#define TKC 64                         // K bytes per chunk / per smem stage
#define NCHUNK (IN_F / TKC)            // 64
#define NMT (TOKENS / TM)              // 64
#define NNT (OUT_F / TN)               // 224
#define GROUP_M 8

#define STAGES 4
#define OFF_ALO 8192
#define OFF_B   16384
#define STAGE_BYTES 20480              // A_hi 8K + A_lo 8K + B 4K
#define SMEM_DYN (STAGES * STAGE_BYTES)   // 81920

// ---------------------------------------------------------------------------
// Device-global scratch (static allocation — no runtime allocs allowed)
// ---------------------------------------------------------------------------
__device__ int8_t g_qh[(size_t)TOKENS * IN_F];   // high s8 plane of quantized x
__device__ int8_t g_ql[(size_t)TOKENS * IN_F];   // low  s8 plane
__device__ int8_t g_w8[(size_t)OUT_F * IN_F];    // expanded nibbles (0..15) as s8
__device__ float  g_rs[TOKENS];                  // per-row sum of x
__device__ float  g_stq[TOKENS];                 // per-row quant scale s_t
__device__ float  g_inv[TOKENS];                 // 1 / s_t

// ---------------------------------------------------------------------------
// small helpers
// ---------------------------------------------------------------------------
__device__ __forceinline__ uint32_t smem_u32(const void* p) {
    uint32_t a;
    asm("{ .reg .u64 t; cvta.to.shared.u64 t, %1; cvt.u32.u64 %0, t; }"
        : "=r"(a) : "l"(p));
    return a;
}

__device__ __forceinline__ void cp_async16(uint32_t dst, const void* src) {
    asm volatile("cp.async.cg.shared.global [%0], [%1], 16;"
                 :: "r"(dst), "l"(src) : "memory");
}
__device__ __forceinline__ void cp_commit() {
    asm volatile("cp.async.commit_group;" ::: "memory");
}

__device__ __forceinline__ void ldsm_x4(uint32_t* a, uint32_t addr) {
    asm volatile("ldmatrix.sync.aligned.m8n8.x4.shared.b16 {%0,%1,%2,%3}, [%4];"
                 : "=r"(a[0]), "=r"(a[1]), "=r"(a[2]), "=r"(a[3]) : "r"(addr));
}

__device__ __forceinline__ void mma_s8(int* d, const uint32_t* a, const uint32_t* b) {
    asm volatile(
        "mma.sync.aligned.m16n8k32.row.col.s32.s8.s8.s32 "
        "{%0,%1,%2,%3}, {%4,%5,%6,%7}, {%8,%9}, {%0,%1,%2,%3};"
        : "+r"(d[0]), "+r"(d[1]), "+r"(d[2]), "+r"(d[3])
        : "r"(a[0]), "r"(a[1]), "r"(a[2]), "r"(a[3]), "r"(b[0]), "r"(b[1]));
}

__device__ __forceinline__ void lds128(uint32_t* v, uint32_t addr) {
    asm volatile("ld.shared.v4.b32 {%0,%1,%2,%3}, [%4];"
                 : "=r"(v[0]), "=r"(v[1]), "=r"(v[2]), "=r"(v[3]) : "r"(addr));
}

// ---------------------------------------------------------------------------
// Preprocess 1: per-row sum + quantization scale
// ---------------------------------------------------------------------------
__global__ __launch_bounds__(256)
void rowstat_kernel(const float* __restrict__ x) {
    const int row = blockIdx.x;
    const float4* xr = (const float4*)(x + (size_t)row * IN_F);
    float s = 0.f, m = 0.f;
#pragma unroll
    for (int i = 0; i < 4; i++) {
        float4 f = __ldg(xr + threadIdx.x + i * 256);
        s += (f.x + f.y) + (f.z + f.w);
        m = fmaxf(m, fmaxf(fmaxf(fabsf(f.x), fabsf(f.y)), fmaxf(fabsf(f.z), fabsf(f.w))));
    }
#pragma unroll
    for (int o = 16; o; o >>= 1) {
        s += __shfl_xor_sync(0xFFFFFFFFu, s, o);
        m = fmaxf(m, __shfl_xor_sync(0xFFFFFFFFu, m, o));
    }
    __shared__ float rs[8], rm[8];
    if ((threadIdx.x & 31) == 0) { rs[threadIdx.x >> 5] = s; rm[threadIdx.x >> 5] = m; }
    __syncthreads();
    if (threadIdx.x == 0) {
        float ts = 0.f, tm = 0.f;
#pragma unroll
        for (int j = 0; j < 8; j++) { ts += rs[j]; tm = fmaxf(tm, rm[j]); }
        g_rs[row] = ts;
        if (tm > 0.f) { g_stq[row] = tm / 32512.f; g_inv[row] = 32512.f / tm; }
        else          { g_stq[row] = 0.f;          g_inv[row] = 0.f; }
    }
}

// ---------------------------------------------------------------------------
// Preprocess 2: quantize x -> (qh, ql) s8 planes.
// ---------------------------------------------------------------------------
__global__ __launch_bounds__(256)
void quantx_kernel(const float* __restrict__ x) {
    const int id  = blockIdx.x * 256 + threadIdx.x;
    const int row = id >> 9;
    const int kc  = (id & 511) * 8;
    const float inv = __ldg(g_inv + row);
    const float4* p = (const float4*)(x + (size_t)row * IN_F + kc);
    float4 f0 = __ldg(p), f1 = __ldg(p + 1);
    int q[8];
    q[0] = __float2int_rn(f0.x * inv); q[1] = __float2int_rn(f0.y * inv);
    q[2] = __float2int_rn(f0.z * inv); q[3] = __float2int_rn(f0.w * inv);
    q[4] = __float2int_rn(f1.x * inv); q[5] = __float2int_rn(f1.y * inv);
    q[6] = __float2int_rn(f1.z * inv); q[7] = __float2int_rn(f1.w * inv);
    uint32_t h0 = 0, h1 = 0, l0 = 0, l1 = 0;
#pragma unroll
    for (int i = 0; i < 4; i++) {
        int qh = (q[i] + 128) >> 8;
        int ql = q[i] - (qh << 8);
        h0 |= ((uint32_t)qh & 0xFFu) << (8 * i);
        l0 |= ((uint32_t)ql & 0xFFu) << (8 * i);
        int qh2 = (q[4 + i] + 128) >> 8;
        int ql2 = q[4 + i] - (qh2 << 8);
        h1 |= ((uint32_t)qh2 & 0xFFu) << (8 * i);
        l1 |= ((uint32_t)ql2 & 0xFFu) << (8 * i);
    }
    *(uint2*)(g_qh + (size_t)row * IN_F + kc) = make_uint2(h0, h1);
    *(uint2*)(g_ql + (size_t)row * IN_F + kc) = make_uint2(l0, l1);
}

// ---------------------------------------------------------------------------
// Preprocess 3: expand packed nibbles to s8 bytes (0..15 exact).
// ---------------------------------------------------------------------------
__global__ __launch_bounds__(256)
void expw_kernel(const int* __restrict__ pw) {
    const size_t id = (size_t)blockIdx.x * 256 + threadIdx.x;
    int4 p = __ldg((const int4*)pw + id);
    uint32_t w0 = (uint32_t)(p.x & 0xF) | ((uint32_t)(p.x & 0xF0) << 4)
                | ((uint32_t)(p.y & 0xF) << 16) | ((uint32_t)(p.y & 0xF0) << 20);
    uint32_t w1 = (uint32_t)(p.z & 0xF) | ((uint32_t)(p.z & 0xF0) << 4)
                | ((uint32_t)(p.w & 0xF) << 16) | ((uint32_t)(p.w & 0xF0) << 20);
    ((uint2*)g_w8)[id] = make_uint2(w0, w1);
}

// ---------------------------------------------------------------------------
// GEMM: 128x64 tile, 256 threads, 2 CTAs/SM.  R13 work split (tensor warps:
// full hi plane; fma warps: full lo plane; shared coalesced fills).
// Tensor-warp change vs R13: B fragments via ldmatrix.x4 (8 ldmatrix ops per
// chunk instead of 32 LDS.32 + 4 ldsm) with ks-level double buffering so
// ks=1 fragment loads issue under the ks=0 mma stream.  ALL fragment loads
// happen AFTER the __syncthreads (which is what makes every warp's cp.async
// fills of stage ch visible — fixing R15's race).
// ---------------------------------------------------------------------------
__global__ __launch_bounds__(256, 2)
void gemm_kernel(const float* __restrict__ scales, const float* __restrict__ zps,
                 float* __restrict__ out) {
    extern __shared__ char smem[];
    const uint32_t sbase = smem_u32(smem);

    const int tid = threadIdx.x;
    const int l   = tid & 31;
    const int wid = tid >> 5;
    const bool tw = (wid < 4);         // tensor warp?
    const int wm  = wid & 3;           // row-block (0..3) for BOTH roles

    const int per_group = GROUP_M * NNT;
    const int grp = blockIdx.x / per_group;
    const int rem = blockIdx.x - grp * per_group;
    const int m0 = (grp * GROUP_M + (rem % GROUP_M)) * TM;
    const int n0 = (rem / GROUP_M) * TN;

    // ---- pipeline fill (R8 pattern): per thread 2x A_hi, 2x A_lo, 1x B ----
    const int frow = tid >> 2;              // 0..63
    const int fg   = tid & 3;
    const uint32_t fsw = (uint32_t)((fg ^ ((frow >> 1) & 3)) << 4);
    const uint32_t d1 = (uint32_t)frow * 64 + fsw;
    const uint32_t d2 = d1 + 64 * 64;
    const int8_t* srcA_h1 = g_qh + (size_t)(m0 + frow) * IN_F + fg * 16;
    const int8_t* srcA_h2 = g_qh + (size_t)(m0 + 64 + frow) * IN_F + fg * 16;
    const int8_t* srcA_l1 = g_ql + (size_t)(m0 + frow) * IN_F + fg * 16;
    const int8_t* srcA_l2 = g_ql + (size_t)(m0 + 64 + frow) * IN_F + fg * 16;
    const int8_t* srcB    = g_w8 + (size_t)(n0 + frow) * IN_F + fg * 16;

#define FILL(ch, stage) do {                                                  \
        uint32_t st_ = sbase + (uint32_t)(stage) * STAGE_BYTES;               \
        int k0_ = (ch) * TKC;                                                 \
        cp_async16(st_ + d1,                 srcA_h1 + k0_);                  \
        cp_async16(st_ + d2,                 srcA_h2 + k0_);                  \
        cp_async16(st_ + OFF_ALO + d1,       srcA_l1 + k0_);                  \
        cp_async16(st_ + OFF_ALO + d2,       srcA_l2 + k0_);                  \
        cp_async16(st_ + OFF_B + d1,         srcB    + k0_);                  \
    } while (0)

    FILL(0, 0); cp_commit();
    FILL(1, 1); cp_commit();
    FILL(2, 2); cp_commit();

    // ---- tensor-warp lane constants ----
    // A ldsm row/key (key identical for mt=0/1: rows differ by 16)
    const int lm_row = (((l >> 3) & 1) << 3) + (l & 7);
    const int lm_g   = (l >> 4) & 1;
    const int aRow0  = wm * 32 + lm_row;               // mt=0 row
    const uint32_t aKey = (uint32_t)((aRow0 >> 1) & 3);
    // B ldmatrix.x4: addr lane j supplies matrix j>>3, row j&7.
    // Per t (0..3): matrices = (rows 16t+0..7, half0), (16t+0..7, half1),
    //               (16t+8..15, half0), (16t+8..15, half1)
    //  -> fragments b[2t][0], b[2t][1], b[2t+1][0], b[2t+1][1].
    const int rB = (((l >> 4) & 1) << 3) + (l & 7);    // row 0..15 within t-block
    const int hB = (l >> 3) & 1;                       // k-half selector
    const uint32_t kB = (uint32_t)((rB >> 1) & 3);
    const uint32_t bA0 = OFF_B + (uint32_t)rB * 64 + ((((uint32_t)hB) ^ kB) << 4);
    const uint32_t bA1 = OFF_B + (uint32_t)rB * 64 + ((((uint32_t)(2 + hB)) ^ kB) << 4);

    // ---- fma-warp lane constants ----
    const int r0 = l >> 2;
    const uint32_t swA = (uint32_t)((r0 >> 1) & 3);
    const uint32_t swB = (uint32_t)(l & 3);
    const uint32_t aRowBase = (uint32_t)(wm * 32 + r0) * 64;

    // accumulators: tensor -> acc[mt*32+nt*4+c]; fma -> acc[ri*16+ci]
    int acc[64];
#pragma unroll
    for (int i = 0; i < 64; i++) acc[i] = 0;

    for (int ch = 0; ch < NCHUNK; ch++) {
        asm volatile("cp.async.wait_group 2;" ::: "memory");
        __syncthreads();   // makes ALL warps' fills of stage ch visible

        if (ch + STAGES - 1 < NCHUNK) FILL(ch + STAGES - 1, (ch + STAGES - 1) & 3);
        cp_commit();

        const uint32_t st = sbase + (uint32_t)(ch & 3) * STAGE_BYTES;

        if (tw) {
            uint32_t b0[8][2], b1[8][2], aA[4], aB[4];
            // ---- ks=0 fragments ----
#pragma unroll
            for (int t = 0; t < 4; t++) {
                uint32_t tmp[4];
                ldsm_x4(tmp, st + bA0 + (uint32_t)t * 1024);
                b0[2 * t][0] = tmp[0];      b0[2 * t][1] = tmp[1];
                b0[2 * t + 1][0] = tmp[2];  b0[2 * t + 1][1] = tmp[3];
            }
            ldsm_x4(aA, st + (uint32_t)aRow0 * 64
                         + ((((uint32_t)lm_g) ^ aKey) << 4));          // (ks0,mt0)
            ldsm_x4(aB, st + (uint32_t)(aRow0 + 16) * 64
                         + ((((uint32_t)lm_g) ^ aKey) << 4));          // (ks0,mt1)
            // ---- ks=1 B fragments issue under the ks=0 mma stream ----
#pragma unroll
            for (int t = 0; t < 4; t++) {
                uint32_t tmp[4];
                ldsm_x4(tmp, st + bA1 + (uint32_t)t * 1024);
                b1[2 * t][0] = tmp[0];      b1[2 * t][1] = tmp[1];
                b1[2 * t + 1][0] = tmp[2];  b1[2 * t + 1][1] = tmp[3];
            }
#pragma unroll
            for (int nt = 0; nt < 8; nt++) mma_s8(&acc[nt * 4], aA, b0[nt]);
            ldsm_x4(aA, st + (uint32_t)aRow0 * 64
                         + ((((uint32_t)(2 + lm_g)) ^ aKey) << 4));    // (ks1,mt0)
#pragma unroll
            for (int nt = 0; nt < 8; nt++) mma_s8(&acc[32 + nt * 4], aB, b0[nt]);
            ldsm_x4(aB, st + (uint32_t)(aRow0 + 16) * 64
                         + ((((uint32_t)(2 + lm_g)) ^ aKey) << 4));    // (ks1,mt1)
#pragma unroll
            for (int nt = 0; nt < 8; nt++) mma_s8(&acc[nt * 4], aA, b1[nt]);
#pragma unroll
            for (int nt = 0; nt < 8; nt++) mma_s8(&acc[32 + nt * 4], aB, b1[nt]);
        } else {
            // ============ fma warps: lo plane via dp4a (R13 verbatim) =======
#pragma unroll
            for (int g = 0; g < 4; g++) {
                uint32_t a4[4][4];
                const uint32_t aGran = (uint32_t)((g ^ swA) << 4);
#pragma unroll
                for (int ri = 0; ri < 4; ri++)
                    lds128(a4[ri], st + OFF_ALO + aRowBase + (uint32_t)(ri * 8 * 64) + aGran);
                const uint32_t bGran = (uint32_t)((g ^ swB) << 4);
#pragma unroll
                for (int ci = 0; ci < 16; ci++) {
                    uint32_t b4[4];
                    int n = 2 * (l & 3) + (ci & 1) + 8 * (ci >> 1);
                    lds128(b4, st + OFF_B + (uint32_t)n * 64 + bGran);
#pragma unroll
                    for (int w = 0; w < 4; w++)
#pragma unroll
                        for (int ri = 0; ri < 4; ri++)
                            acc[ri * 16 + ci] = __dp4a((int)a4[ri][w], (int)b4[w],
                                                       acc[ri * 16 + ci]);
                }
            }
        }
    }
    asm volatile("cp.async.wait_group 0;" ::: "memory");
    __syncthreads();

    // ---- combine: fma warps publish lo-plane sums through SMEM ----
    int* sD = (int*)smem;                       // [128][65] pitch 65
    if (!tw) {
#pragma unroll
        for (int ri = 0; ri < 4; ri++)
#pragma unroll
            for (int ci = 0; ci < 16; ci++) {
                int row = wm * 32 + r0 + 8 * ri;
                int col = 2 * (l & 3) + (ci & 1) + 8 * (ci >> 1);
                sD[row * 65 + col] = acc[ri * 16 + ci];
            }
    }
    __syncthreads();

    // ---- epilogue (tensor warps): out = sc*(s_t*((hi<<8)+lo) - zp*rs) ----
    if (tw) {
#pragma unroll
        for (int mt = 0; mt < 2; mt++) {
            const int lr0 = wm * 32 + mt * 16 + (l >> 2);
            const int rr0 = m0 + lr0;
            const float st0 = __ldg(g_stq + rr0),     rs0 = __ldg(g_rs + rr0);
            const float st1 = __ldg(g_stq + rr0 + 8), rs1 = __ldg(g_rs + rr0 + 8);
#pragma unroll
            for (int nt = 0; nt < 8; nt++) {
                const int lc = nt * 8 + 2 * (l & 3);
                const int c  = n0 + lc;
                const float sc0 = __ldg(scales + c), sc1 = __ldg(scales + c + 1);
                const float zp0 = __ldg(zps + c),    zp1 = __ldg(zps + c + 1);
                int A0 = (acc[mt * 32 + nt * 4 + 0] << 8) + sD[lr0 * 65 + lc];
                int A1 = (acc[mt * 32 + nt * 4 + 1] << 8) + sD[lr0 * 65 + lc + 1];
                int A2 = (acc[mt * 32 + nt * 4 + 2] << 8) + sD[(lr0 + 8) * 65 + lc];
                int A3 = (acc[mt * 32 + nt * 4 + 3] << 8) + sD[(lr0 + 8) * 65 + lc + 1];
                float2 v0 = make_float2(sc0 * (st0 * (float)A0 - zp0 * rs0),
                                        sc1 * (st0 * (float)A1 - zp1 * rs0));
                float2 v1 = make_float2(sc0 * (st1 * (float)A2 - zp0 * rs1),
                                        sc1 * (st1 * (float)A3 - zp1 * rs1));
                *(float2*)(out + (size_t)rr0 * OUT_F + c)       = v0;
                *(float2*)(out + (size_t)(rr0 + 8) * OUT_F + c) = v1;
            }
        }
    }
#undef FILL
}

// ---------------------------------------------------------------------------
// Launch
// ---------------------------------------------------------------------------
extern "C" void kernel_launch(void* const* d_in, const int* in_sizes, int n_in,
                              void* d_out, int out_size) {
    const float* x  = (const float*)d_in[0];
    const int*   pw = (const int*)d_in[1];
    const float* sc = (const float*)d_in[2];
    const float* zp = (const float*)d_in[3];
    float* out = (float*)d_out;

    cudaFuncSetAttribute(gemm_kernel, cudaFuncAttributeMaxDynamicSharedMemorySize, SMEM_DYN);

    rowstat_kernel<<<TOKENS, 256>>>(x);
    quantx_kernel<<<(TOKENS * (IN_F / 8)) / 256, 256>>>(x);
    expw_kernel<<<(int)(((size_t)OUT_F * (IN_F / 2) / 4) / 256), 256>>>(pw);
    gemm_kernel<<<NMT * NNT, 256, SMEM_DYN>>>(sc, zp, out);

    (void)in_sizes; (void)n_in; (void)out_size;
}